// round 17
// baseline (speedup 1.0000x reference)
#include <cuda_runtime.h>
#include <cuda_fp16.h>
#include <cstdint>

// ---------------- problem constants ----------------
namespace {
constexpr int CB  = 4;      // batch
constexpr int CS  = 1024;   // seq
constexpr int CD  = 1280;   // model dim
constexpr int CH  = 16;     // heads
constexpr int CHD = 80;     // head dim
constexpr int CM  = CB * CS;          // 4096 rows
constexpr int CNQKV = 3 * CD;         // 3840
constexpr int KP  = CD / 2;           // 640 fp16 pairs per row

// dense GEMM (CTA 128x128, 4 warps 2x2, warp tile 64x64), fp16, 3-stage,
// chunk = 32 pairs stored as two 128x16 pitch-16 blocks (conflict-free).
constexpr int BLKU  = 128 * 16;                // u32 per block = 2048
constexpr int SSTG2 = 4 * BLKU;                // A(2 blk) + B(2 blk) = 8192 u32
constexpr int NSTAGE = 3;
constexpr int GEMM_SMEM = NSTAGE * SSTG2 * 4;  // 98,304 B (x2 CTAs = 192KB)

// attention smem (u32 units): Q[128] + double-buffered K[64]/V[80].
constexpr int PQH = 40;
constexpr int PKH = 40;
constexpr int PVH = 40;
constexpr int OQ   = 0;
constexpr int OK0  = OQ + 128 * PQH;       // 5120
constexpr int OK1  = OK0 + 64 * PKH;       // 7680
constexpr int OV0  = OK1 + 64 * PKH;       // 10240
constexpr int OV1  = OV0 + 80 * PVH;       // 13440
constexpr int ATTN_U32 = OV1 + 80 * PVH;   // 16640
constexpr int ATTN_SMEM = ATTN_U32 * 4;    // 66,560 B (x2 CTAs = 133KB)

// merged prep kernel block ranges
constexpr int PREP_A_BLKS  = CM * KP / 256;            // 10240
constexpr int PREP_B0_NB   = CNQKV / 32;               // 120
constexpr int PREP_B0_BLKS = PREP_B0_NB * (CD / 32);   // 4800
constexpr int PREP_B1_NB   = CD / 32;                  // 40
constexpr int PREP_B1_BLKS = PREP_B1_NB * (CD / 32);   // 1600
constexpr int PREP_TOTAL   = PREP_A_BLKS + PREP_B0_BLKS + PREP_B1_BLKS;
}
#define ATTN_SCALE 0.11180339887498948f  // 80^-0.5
#define LOG2E      1.4426950408889634f

// ---------------- scratch (device globals; no allocs allowed) ----------------
__device__ __align__(16) float    g_q[CB * CH * CS * CHD];      // fp32 (pre-rope)
__device__ __align__(16) float    g_k[CB * CH * CS * CHD];      // fp32 (pre-rope)
__device__ __align__(16) uint32_t g_qp[CB * CH * CS * (CHD/2)]; // fp16x2, roped, *SCALE*log2e, 8-interleaved
__device__ __align__(16) uint32_t g_kp[CB * CH * CS * (CHD/2)]; // fp16x2, roped, 8-interleaved
__device__ __align__(16) __half   g_vt[CB * CH * CHD * CS];     // fp16, [b,h,d,s] s-pairs 8-interleaved
// fp16x2 pair-permuted GEMM operands
__device__ __align__(16) uint32_t g_xp[CM * KP];               // [m][p']
__device__ __align__(16) uint32_t g_ctxp[CM * KP];             // [m][p'] (from attn)
__device__ __align__(16) uint32_t g_wqkvp[CNQKV * KP];         // [n][p'] (transposed)
__device__ __align__(16) uint32_t g_wprojp[CD * KP];           // [n][p']

// ---------------- helpers ----------------
__device__ __forceinline__ uint32_t f2h2(float lo, float hi) {
    __half2 h = __floats2half2_rn(lo, hi);
    return *reinterpret_cast<uint32_t*>(&h);
}
__device__ __forceinline__ void mma_f16(float c[4],
                                        uint32_t a0, uint32_t a1, uint32_t a2, uint32_t a3,
                                        uint32_t b0, uint32_t b1) {
    asm volatile(
        "mma.sync.aligned.m16n8k16.row.col.f32.f16.f16.f32 "
        "{%0,%1,%2,%3}, {%4,%5,%6,%7}, {%8,%9}, {%0,%1,%2,%3};"
        : "+f"(c[0]), "+f"(c[1]), "+f"(c[2]), "+f"(c[3])
        : "r"(a0), "r"(a1), "r"(a2), "r"(a3), "r"(b0), "r"(b1));
}
__device__ __forceinline__ uint32_t smem_u32(const void* p) {
    uint32_t a;
    asm("{ .reg .u64 t; cvta.to.shared.u64 t, %1; cvt.u32.u64 %0, t; }"
        : "=r"(a) : "l"(p));
    return a;
}
__device__ __forceinline__ void cpasync16(uint32_t dst, const void* src) {
    asm volatile("cp.async.cg.shared.global [%0], [%1], 16;" :: "r"(dst), "l"(src));
}
// 4x4 pair permutation within each 16-pair block (involution): w' = (w%4)*4 + w/4
__device__ __forceinline__ int pperm(int p) {
    const int b = p & ~15, w = p & 15;
    return b + (w & 3) * 4 + (w >> 2);
}
// 8-group interleave [0,4,1,5,2,6,3,7]: pair w -> position 2*(w&3) + (w>>2)
__device__ __forceinline__ int ip8(int p) {
    const int b = p & ~7, w = p & 7;
    return b + 2 * (w & 3) + (w >> 2);
}

// ============================================================================
// Merged prep kernel: one launch does permA0 + transB(Wqkv) + transB(Wproj).
// ============================================================================
__global__ void __launch_bounds__(256)
prep_all(const float* __restrict__ x,
         const float* __restrict__ Wqkv,
         const float* __restrict__ Wproj)
{
    const int blk = blockIdx.x;
    const int tid = threadIdx.x;

    if (blk < PREP_A_BLKS) {
        const int i = blk * 256 + tid;
        const int m  = i / KP;
        const int pp = i - m * KP;
        const int pair = pperm(pp);
        const float* s = x + (size_t)m * CD + 2 * pair;
        g_xp[i] = f2h2(s[0], s[1]);
        return;
    }

    const bool is0 = (blk < PREP_A_BLKS + PREP_B0_BLKS);
    const int  rb  = blk - (is0 ? PREP_A_BLKS : PREP_A_BLKS + PREP_B0_BLKS);
    const float* __restrict__ W = is0 ? Wqkv : Wproj;
    uint32_t* __restrict__ out  = is0 ? g_wqkvp : g_wprojp;
    const int N  = is0 ? CNQKV : CD;
    const int NB = is0 ? PREP_B0_NB : PREP_B1_NB;
    const int nb = rb % NB;
    const int kb = rb / NB;

    __shared__ float tile[32][33];
    const int tx = tid & 31, ty = tid >> 5;
    #pragma unroll
    for (int r = 0; r < 4; r++) {
        const int kl = ty + 8 * r;
        tile[kl][tx] = W[(size_t)(kb * 32 + kl) * N + nb * 32 + tx];
    }
    __syncthreads();
    #pragma unroll
    for (int i = 0; i < 2; i++) {
        const int o = tid + 256 * i;
        const int n  = o >> 4;
        const int w1 = o & 15;
        const int w  = (w1 & 3) * 4 + (w1 >> 2);
        out[(size_t)(nb * 32 + n) * KP + kb * 16 + w1] =
            f2h2(tile[2 * w][n], tile[2 * w + 1][n]);
    }
}

// ============================================================================
// fp16 mma.sync GEMM (R15/16 winner): chunk = 32 pairs.
// MODE 0: scatter q/k fp32 + v fp16 [b,h,d,s] (s-pairs 8-interleaved).
// MODE 1: -> out fp32.
// ============================================================================
template <int MODE>
__global__ void __launch_bounds__(128)
gemm_h2(const float* __restrict__ bias, float* __restrict__ out, int N)
{
    const uint32_t* __restrict__ Ap = MODE ? g_ctxp : g_xp;
    const uint32_t* __restrict__ Bp = MODE ? g_wprojp : g_wqkvp;

    extern __shared__ uint32_t smu[];
    const uint32_t smbase = smem_u32(smu);

    const int tid  = threadIdx.x;
    const int wid  = tid >> 5;
    const int lane = tid & 31;
    const int g    = lane >> 2;
    const int t    = lane & 3;
    const int wm   = wid & 1;
    const int wn   = wid >> 1;
    const int m0   = blockIdx.y * 128;
    const int n0   = blockIdx.x * 128;

    float cf[4][8][4];
    #pragma unroll
    for (int im = 0; im < 4; im++)
        #pragma unroll
        for (int in = 0; in < 8; in++)
            #pragma unroll
            for (int r = 0; r < 4; r++) cf[im][in][r] = 0.f;

    auto issue = [&](int c, int p) {
        const uint32_t abase = smbase + (uint32_t)p * SSTG2 * 4;
        const uint32_t bbase = abase + 2 * BLKU * 4;
        const int p0 = c * 32;
        #pragma unroll
        for (int i = 0; i < 8; i++) {
            const int s = tid + 128 * i;
            const int row = s >> 3, seg = s & 7;
            const uint32_t dst = abase +
                (uint32_t)((seg >> 2) * BLKU + row * 16 + (seg & 3) * 4) * 4;
            cpasync16(dst, Ap + (size_t)(m0 + row) * KP + p0 + seg * 4);
        }
        #pragma unroll
        for (int i = 0; i < 8; i++) {
            const int s = tid + 128 * i;
            const int row = s >> 3, seg = s & 7;
            const uint32_t dst = bbase +
                (uint32_t)((seg >> 2) * BLKU + row * 16 + (seg & 3) * 4) * 4;
            cpasync16(dst, Bp + (size_t)(n0 + row) * KP + p0 + seg * 4);
        }
        asm volatile("cp.async.commit_group;" ::: "memory");
    };

    const int NCH = KP / 32;   // 20
    issue(0, 0);
    issue(1, 1);

    for (int c = 0; c < NCH; c++) {
        const int p = c % NSTAGE;
        if (c + 1 < NCH) {
            asm volatile("cp.async.wait_group 1;" ::: "memory");
        } else {
            asm volatile("cp.async.wait_group 0;" ::: "memory");
        }
        __syncthreads();

        const uint32_t* As = smu + p * SSTG2;
        const uint32_t* Bs = As + 2 * BLKU;

        uint4 a0f[4][2], b0f[8];
        #pragma unroll
        for (int im = 0; im < 4; im++) {
            const int row = wm * 64 + im * 16 + g;
            a0f[im][0] = *reinterpret_cast<const uint4*>(As + row * 16 + t * 4);
            a0f[im][1] = *reinterpret_cast<const uint4*>(As + (row + 8) * 16 + t * 4);
        }
        #pragma unroll
        for (int in = 0; in < 8; in++) {
            const int n = wn * 64 + in * 8 + g;
            b0f[in] = *reinterpret_cast<const uint4*>(Bs + n * 16 + t * 4);
        }

        if (c + 2 < NCH) issue(c + 2, (c + 2) % NSTAGE);

        #pragma unroll
        for (int ks = 0; ks < 2; ks++) {
            #pragma unroll
            for (int im = 0; im < 4; im++) {
                const uint32_t a0 = ks ? a0f[im][0].z : a0f[im][0].x;
                const uint32_t a2 = ks ? a0f[im][0].w : a0f[im][0].y;
                const uint32_t a1 = ks ? a0f[im][1].z : a0f[im][1].x;
                const uint32_t a3 = ks ? a0f[im][1].w : a0f[im][1].y;
                #pragma unroll
                for (int in = 0; in < 8; in++) {
                    const uint32_t b0 = ks ? b0f[in].z : b0f[in].x;
                    const uint32_t b1 = ks ? b0f[in].w : b0f[in].y;
                    mma_f16(cf[im][in], a0, a1, a2, a3, b0, b1);
                }
            }
        }

        {
            const uint32_t* Ab = As + BLKU;
            const uint32_t* Bb = Bs + BLKU;
            uint4 a[4][2], b[8];
            #pragma unroll
            for (int im = 0; im < 4; im++) {
                const int row = wm * 64 + im * 16 + g;
                a[im][0] = *reinterpret_cast<const uint4*>(Ab + row * 16 + t * 4);
                a[im][1] = *reinterpret_cast<const uint4*>(Ab + (row + 8) * 16 + t * 4);
            }
            #pragma unroll
            for (int in = 0; in < 8; in++) {
                const int n = wn * 64 + in * 8 + g;
                b[in] = *reinterpret_cast<const uint4*>(Bb + n * 16 + t * 4);
            }
            #pragma unroll
            for (int ks = 0; ks < 2; ks++) {
                #pragma unroll
                for (int im = 0; im < 4; im++) {
                    const uint32_t a0 = ks ? a[im][0].z : a[im][0].x;
                    const uint32_t a2 = ks ? a[im][0].w : a[im][0].y;
                    const uint32_t a1 = ks ? a[im][1].z : a[im][1].x;
                    const uint32_t a3 = ks ? a[im][1].w : a[im][1].y;
                    #pragma unroll
                    for (int in = 0; in < 8; in++) {
                        const uint32_t b0 = ks ? b[in].z : b[in].x;
                        const uint32_t b1 = ks ? b[in].w : b[in].y;
                        mma_f16(cf[im][in], a0, a1, a2, a3, b0, b1);
                    }
                }
            }
        }
    }
    __syncthreads();

    // ---- epilogue ----
    #pragma unroll
    for (int im = 0; im < 4; im++) {
        #pragma unroll
        for (int in = 0; in < 8; in++) {
            const int mrow0 = m0 + wm * 64 + im * 16 + g;
            const int ncol  = n0 + wn * 64 + in * 8 + 2 * t;
            const float2 bb = *reinterpret_cast<const float2*>(bias + ncol);
            #pragma unroll
            for (int h2 = 0; h2 < 2; h2++) {
                const int m = mrow0 + h2 * 8;
                float2 v;
                v.x = cf[im][in][h2 * 2 + 0] + bb.x;
                v.y = cf[im][in][h2 * 2 + 1] + bb.y;
                if (MODE == 0) {
                    const int b = m >> 10;
                    const int s = m & 1023;
                    const int which = ncol / CD;        // 0=q 1=k 2=v
                    const int r = ncol - which * CD;
                    const int h = r / CHD;
                    const int d = r - h * CHD;
                    if (which == 0) {
                        *reinterpret_cast<float2*>(
                            g_q + ((size_t)(b * CH + h) * CS + s) * CHD + d) = v;
                    } else if (which == 1) {
                        *reinterpret_cast<float2*>(
                            g_k + ((size_t)(b * CH + h) * CS + s) * CHD + d) = v;
                    } else {
                        const int sp = 2 * ip8(s >> 1) + (s & 1);
                        const size_t vbase = ((size_t)(b * CH + h) * CHD + d) * CS + sp;
                        g_vt[vbase]      = __float2half_rn(v.x);
                        g_vt[vbase + CS] = __float2half_rn(v.y);
                    }
                } else {
                    *reinterpret_cast<float2*>(out + (size_t)m * CD + ncol) = v;
                }
            }
        }
    }
}

// ============================================================================
// RoPE: fp32 q/k -> roped fp16x2, 8-interleaved pair layout.
// q pre-scaled by SCALE*log2e (softmax runs in exp2 domain).
// ============================================================================
__global__ void __launch_bounds__(256)
rope_kernel(const float* __restrict__ cosb, const float* __restrict__ sinb)
{
    const int idx = blockIdx.x * blockDim.x + threadIdx.x;
    constexpr int TOT = CB * CH * CS * 20;
    if (idx >= TOT) return;
    const int j  = idx % 20;
    const int s  = (idx / 20) % CS;
    const int bh = idx / (20 * CS);

    const float QSC = ATTN_SCALE * LOG2E;

    const float2 c2 = *reinterpret_cast<const float2*>(cosb + s * CHD + 2 * j);
    const float2 s2 = *reinterpret_cast<const float2*>(sinb + s * CHD + 2 * j);
    const size_t base  = ((size_t)bh * CS + s) * CHD;
    const size_t pbase = ((size_t)bh * CS + s) * (CHD / 2);
    const int pj0 = ip8(j);
    const int pj1 = ip8(j + 20);

    const float2 q1 = *reinterpret_cast<const float2*>(g_q + base + 2 * j);
    const float2 q2 = *reinterpret_cast<const float2*>(g_q + base + 40 + 2 * j);
    g_qp[pbase + pj0] = f2h2((q1.x * c2.x - q2.x * s2.x) * QSC,
                             (q1.y * c2.y - q2.y * s2.y) * QSC);
    g_qp[pbase + pj1] = f2h2((q2.x * c2.x + q1.x * s2.x) * QSC,
                             (q2.y * c2.y + q1.y * s2.y) * QSC);

    const float2 k1 = *reinterpret_cast<const float2*>(g_k + base + 2 * j);
    const float2 k2 = *reinterpret_cast<const float2*>(g_k + base + 40 + 2 * j);
    g_kp[pbase + pj0] = f2h2(k1.x * c2.x - k2.x * s2.x,
                             k1.y * c2.y - k2.y * s2.y);
    g_kp[pbase + pj1] = f2h2(k2.x * c2.x + k1.x * s2.x,
                             k2.y * c2.y + k1.y * s2.y);
}

// ============================================================================
// Fused flash attention v4: 128 threads / 4 warps, 32 q-rows per warp
// (2 row-groups of 16). K/V fragments loaded ONCE and shared across both
// row-groups -> K/V crossbar bytes halve vs R16. Register softmax, exp2.
// ============================================================================
__global__ void __launch_bounds__(128, 2)
attn_h3()
{
    extern __shared__ uint32_t smu[];
    uint32_t* Qs = smu + OQ;                        // [128][40]
    uint32_t* Ks[2] = { smu + OK0, smu + OK1 };     // [64][40]
    uint32_t* Vt[2] = { smu + OV0, smu + OV1 };     // [80][40]
    const uint32_t smb = smem_u32(smu);
    const uint32_t qb = smb + OQ * 4;
    const uint32_t kbb[2] = { smb + OK0 * 4, smb + OK1 * 4 };
    const uint32_t vbb[2] = { smb + OV0 * 4, smb + OV1 * 4 };

    const int tid  = threadIdx.x;
    const int wid  = tid >> 5;       // warp owns q-rows [32*wid, 32*wid+32)
    const int lane = tid & 31;
    const int g    = lane >> 2;
    const int t    = lane & 3;

    const int bh = blockIdx.y;
    const int q0 = blockIdx.x * 128;

    const uint32_t* __restrict__ Qg = g_qp + (size_t)bh * CS * (CHD / 2);
    const uint32_t* __restrict__ Kg = g_kp + (size_t)bh * CS * (CHD / 2);
    const __half*   __restrict__ Vg = g_vt + (size_t)bh * CHD * CS;

    auto fill_kv = [&](int tt, int p) {
        #pragma unroll
        for (int i = 0; i < 10; i++) {
            const int c = tid + 128 * i;         // 0..1279
            if (c < 640) {                        // K: 64 rows x 10 segs
                const int row = c / 10, seg = c % 10;
                cpasync16(kbb[p] + (uint32_t)(row * PKH + seg * 4) * 4,
                          Kg + (size_t)(tt + row) * 40 + seg * 4);
            } else {                              // V: 80 d-rows x 8 segs
                const int cc = c - 640;
                const int d = cc >> 3, sg = cc & 7;
                cpasync16(vbb[p] + (uint32_t)(d * PVH + sg * 4) * 4,
                          Vg + (size_t)d * CS + tt + sg * 8);
            }
        }
        asm volatile("cp.async.commit_group;" ::: "memory");
    };

    // Q fill: 128 rows x 10 segs = 1280 chunks, 10 per thread
    #pragma unroll
    for (int i = 0; i < 10; i++) {
        const int c = tid + 128 * i;
        const int row = c / 10, seg = c % 10;
        cpasync16(qb + (uint32_t)(row * PQH + seg * 4) * 4,
                  Qg + (size_t)(q0 + row) * 40 + seg * 4);
    }
    asm volatile("cp.async.commit_group;" ::: "memory");
    fill_kv(0, 0);

    float m_[2][2], l_[2][2];
    #pragma unroll
    for (int rg = 0; rg < 2; rg++) {
        m_[rg][0] = -1e30f; m_[rg][1] = -1e30f;
        l_[rg][0] = 0.f;    l_[rg][1] = 0.f;
    }
    float of[2][10][4];
    #pragma unroll
    for (int rg = 0; rg < 2; rg++)
        #pragma unroll
        for (int i = 0; i < 10; i++)
            #pragma unroll
            for (int r = 0; r < 4; r++) of[rg][i][r] = 0.f;

    int p = 0;
    for (int tt = 0; tt < CS; tt += 64, p ^= 1) {
        asm volatile("cp.async.wait_group 0;" ::: "memory");
        __syncthreads();

        if (tt + 64 < CS) fill_kv(tt + 64, p ^ 1);

        const uint32_t* Kb = Ks[p];
        const uint32_t* Vb = Vt[p];

        // ---- S = Q K^T : 2 row-groups x 64 kv, K frags loaded once ----
        float sacc[2][8][4];
        #pragma unroll
        for (int rg = 0; rg < 2; rg++)
            #pragma unroll
            for (int in = 0; in < 8; in++)
                #pragma unroll
                for (int r = 0; r < 4; r++) sacc[rg][in][r] = 0.f;

        #pragma unroll
        for (int ks = 0; ks < 5; ks++) {
            const int off = ks * 8 + 2 * t;
            uint2 qA[2], qB[2];
            #pragma unroll
            for (int rg = 0; rg < 2; rg++) {
                const int row = wid * 32 + rg * 16 + g;
                qA[rg] = *reinterpret_cast<const uint2*>(Qs + row * PQH + off);
                qB[rg] = *reinterpret_cast<const uint2*>(Qs + (row + 8) * PQH + off);
            }
            #pragma unroll
            for (int in = 0; in < 8; in++) {
                const int n = in * 8 + g;
                const uint2 kf = *reinterpret_cast<const uint2*>(Kb + n * PKH + off);
                mma_f16(sacc[0][in], qA[0].x, qB[0].x, qA[0].y, qB[0].y, kf.x, kf.y);
                mma_f16(sacc[1][in], qA[1].x, qB[1].x, qA[1].y, qB[1].y, kf.x, kf.y);
            }
        }

        // ---- register-resident online softmax per row-group (exp2) ----
        float aS[2][2];
        uint32_t pa[2][4][4];
        #pragma unroll
        for (int rg = 0; rg < 2; rg++) {
            float mxL = -1e30f, mxH = -1e30f;
            #pragma unroll
            for (int in = 0; in < 8; in++) {
                mxL = fmaxf(mxL, fmaxf(sacc[rg][in][0], sacc[rg][in][1]));
                mxH = fmaxf(mxH, fmaxf(sacc[rg][in][2], sacc[rg][in][3]));
            }
            mxL = fmaxf(mxL, __shfl_xor_sync(0xffffffffu, mxL, 1));
            mxL = fmaxf(mxL, __shfl_xor_sync(0xffffffffu, mxL, 2));
            mxH = fmaxf(mxH, __shfl_xor_sync(0xffffffffu, mxH, 1));
            mxH = fmaxf(mxH, __shfl_xor_sync(0xffffffffu, mxH, 2));
            const float mnL = fmaxf(m_[rg][0], mxL);
            const float mnH = fmaxf(m_[rg][1], mxH);
            aS[rg][0] = exp2f(m_[rg][0] - mnL);
            aS[rg][1] = exp2f(m_[rg][1] - mnH);
            float rsL = 0.f, rsH = 0.f;
            #pragma unroll
            for (int in = 0; in < 8; in++) {
                sacc[rg][in][0] = exp2f(sacc[rg][in][0] - mnL);
                sacc[rg][in][1] = exp2f(sacc[rg][in][1] - mnL);
                sacc[rg][in][2] = exp2f(sacc[rg][in][2] - mnH);
                sacc[rg][in][3] = exp2f(sacc[rg][in][3] - mnH);
                rsL += sacc[rg][in][0] + sacc[rg][in][1];
                rsH += sacc[rg][in][2] + sacc[rg][in][3];
            }
            rsL += __shfl_xor_sync(0xffffffffu, rsL, 1);
            rsL += __shfl_xor_sync(0xffffffffu, rsL, 2);
            rsH += __shfl_xor_sync(0xffffffffu, rsH, 1);
            rsH += __shfl_xor_sync(0xffffffffu, rsH, 2);
            l_[rg][0] = l_[rg][0] * aS[rg][0] + rsL;  m_[rg][0] = mnL;
            l_[rg][1] = l_[rg][1] * aS[rg][1] + rsH;  m_[rg][1] = mnH;

            #pragma unroll
            for (int ks = 0; ks < 4; ks++) {
                pa[rg][ks][0] = f2h2(sacc[rg][2 * ks][0],     sacc[rg][2 * ks][1]);
                pa[rg][ks][1] = f2h2(sacc[rg][2 * ks][2],     sacc[rg][2 * ks][3]);
                pa[rg][ks][2] = f2h2(sacc[rg][2 * ks + 1][0], sacc[rg][2 * ks + 1][1]);
                pa[rg][ks][3] = f2h2(sacc[rg][2 * ks + 1][2], sacc[rg][2 * ks + 1][3]);
            }
            #pragma unroll
            for (int in = 0; in < 10; in++) {
                of[rg][in][0] *= aS[rg][0]; of[rg][in][1] *= aS[rg][0];
                of[rg][in][2] *= aS[rg][1]; of[rg][in][3] *= aS[rg][1];
            }
        }

        // ---- O += P @ V : V frags loaded once, shared across row-groups ----
        #pragma unroll
        for (int ks = 0; ks < 4; ks++) {
            const int off = ks * 8 + 2 * t;
            #pragma unroll
            for (int in = 0; in < 10; in++) {
                const int n = in * 8 + g;
                const uint2 vf = *reinterpret_cast<const uint2*>(Vb + n * PVH + off);
                mma_f16(of[0][in], pa[0][ks][0], pa[0][ks][1], pa[0][ks][2], pa[0][ks][3], vf.x, vf.y);
                mma_f16(of[1][in], pa[1][ks][0], pa[1][ks][1], pa[1][ks][2], pa[1][ks][3], vf.x, vf.y);
            }
        }
    }

    // ---- epilogue: normalize own rows, write g_ctxp fp16x2 (pperm) ----
    const int b = bh >> 4, h = bh & 15;
    #pragma unroll
    for (int rg = 0; rg < 2; rg++) {
        const float invL = 1.f / l_[rg][0];
        const float invH = 1.f / l_[rg][1];
        const int rL = q0 + wid * 32 + rg * 16 + g;
        const int rH = rL + 8;
        uint32_t* ctxL = g_ctxp + ((size_t)b * CS + rL) * KP;
        uint32_t* ctxH = g_ctxp + ((size_t)b * CS + rH) * KP;
        #pragma unroll
        for (int in = 0; in < 10; in++) {
            const int pairidx = h * 40 + in * 4 + t;
            const int ppos = pperm(pairidx);
            ctxL[ppos] = f2h2(of[rg][in][0] * invL, of[rg][in][1] * invL);
            ctxH[ppos] = f2h2(of[rg][in][2] * invH, of[rg][in][3] * invH);
        }
    }
}

// ============================================================================
// launch
// ============================================================================
extern "C" void kernel_launch(void* const* d_in, const int* in_sizes, int n_in,
                              void* d_out, int out_size)
{
    const float* x        = (const float*)d_in[0];
    const float* rope_cos = (const float*)d_in[1];
    const float* rope_sin = (const float*)d_in[2];
    const float* Wqkv     = (const float*)d_in[3];
    const float* bqkv     = (const float*)d_in[4];
    const float* Wproj    = (const float*)d_in[5];
    const float* bproj    = (const float*)d_in[6];
    float* out            = (float*)d_out;

    // 0) merged prep: x + both weights -> fp16x2 permuted operands
    prep_all<<<PREP_TOTAL, 256>>>(x, Wqkv, Wproj);

    // 1) QKV projection -> g_q/g_k (fp32), g_vt (fp16, interleaved)
    cudaFuncSetAttribute(gemm_h2<0>, cudaFuncAttributeMaxDynamicSharedMemorySize, GEMM_SMEM);
    gemm_h2<0><<<dim3(CNQKV / 128, CM / 128), 128, GEMM_SMEM>>>(bqkv, nullptr, CNQKV);

    // 2) RoPE -> g_qp (fp16, scaled by SCALE*log2e, interleaved), g_kp
    {
        const int tot = CB * CH * CS * 20;
        rope_kernel<<<(tot + 255) / 256, 256>>>(rope_cos, rope_sin);
    }

    // 3) fused flash attention (32 q-rows/warp) -> g_ctxp
    cudaFuncSetAttribute(attn_h3, cudaFuncAttributeMaxDynamicSharedMemorySize, ATTN_SMEM);
    attn_h3<<<dim3(CS / 128, CB * CH), 128, ATTN_SMEM>>>();

    // 4) output projection -> d_out
    cudaFuncSetAttribute(gemm_h2<1>, cudaFuncAttributeMaxDynamicSharedMemorySize, GEMM_SMEM);
    gemm_h2<1><<<dim3(CD / 128, CM / 128), 128, GEMM_SMEM>>>(bproj, out, CD);
}